// round 12
// baseline (speedup 1.0000x reference)
#include <cuda_runtime.h>
#include <cuda_bf16.h>

#define DD  512    // model dim
#define EE  32     // experts
#define HH  512    // hidden per gate branch
#define GROWS 1024 // 2*HH gate rows per expert
#define LL  512    // tokens
#define TPB 256

// ---------------- scratch (static device globals; no allocs) ----------------
__device__ int            g_cnt[EE];
__device__ int            g_tok[EE][LL];
__device__ float          g_wt [EE][LL];
__device__ unsigned char  g_kis[EE][LL];
__device__ __align__(16) float g_act[EE][LL][HH];     // 32 MB
__device__ __align__(16) float g_buf[2][LL * DD];     // 2 MB

// ---------------- helpers ----------------
__device__ __forceinline__ float warp_sum(float s) {
    #pragma unroll
    for (int o = 16; o; o >>= 1) s += __shfl_xor_sync(0xffffffffu, s, o);
    return s;
}
__device__ __forceinline__ float gelu_tanh(float g) {
    float inner = 0.7978845608028654f * (g + 0.044715f * g * g * g);
    return 0.5f * g * (1.f + tanhf(inner));
}

// ---------------- K0: zero counters ----------------
__global__ void k0_zero() {
    if (threadIdx.x < EE) g_cnt[threadIdx.x] = 0;
}

// ---------------- K1: routing (one block per token) ----------------
__global__ __launch_bounds__(TPB) void k1_router(
    const float* __restrict__ x, const float* __restrict__ router_scale,
    const float* __restrict__ Wr, const float* __restrict__ escale)
{
    const int tok = blockIdx.x, t = threadIdx.x, lane = t & 31, wid = t >> 5;

    __shared__ float srin[DD];
    __shared__ float spart[8][EE];
    __shared__ float sred[8];

    const float* xrow = x + (size_t)tok * DD;
    float v0 = xrow[t], v1 = xrow[t + TPB];
    float ss = warp_sum(v0 * v0 + v1 * v1);
    if (lane == 0) sred[wid] = ss;
    __syncthreads();
    if (t == 0) {
        float tot = 0.f;
        #pragma unroll
        for (int i = 0; i < 8; i++) tot += sred[i];
        sred[0] = rsqrtf(tot / (float)DD + 1e-6f) * rsqrtf((float)DD);
    }
    __syncthreads();
    const float scl = sred[0];
    srin[t]       = v0 * scl * router_scale[t];
    srin[t + TPB] = v1 * scl * router_scale[t + TPB];
    __syncthreads();

    // router logits: warp w covers d in [64w, 64w+64), lane = expert
    {
        float acc = 0.f;
        const int d0 = wid * 64;
        #pragma unroll 8
        for (int i = 0; i < 64; i++)
            acc = fmaf(srin[d0 + i], Wr[(d0 + i) * EE + lane], acc);
        spart[wid][lane] = acc;
    }
    __syncthreads();

    if (wid == 0) {
        float l = 0.f;
        #pragma unroll
        for (int i = 0; i < 8; i++) l += spart[i][lane];

        float m1 = l; int i1 = lane;
        #pragma unroll
        for (int o = 16; o; o >>= 1) {
            float om = __shfl_xor_sync(0xffffffffu, m1, o);
            int   oi = __shfl_xor_sync(0xffffffffu, i1, o);
            if (om > m1 || (om == m1 && oi < i1)) { m1 = om; i1 = oi; }
        }
        float l2 = (lane == i1) ? -3.4e38f : l;
        float m2 = l2; int i2 = lane;
        #pragma unroll
        for (int o = 16; o; o >>= 1) {
            float om = __shfl_xor_sync(0xffffffffu, m2, o);
            int   oi = __shfl_xor_sync(0xffffffffu, i2, o);
            if (om > m2 || (om == m2 && oi < i2)) { m2 = om; i2 = oi; }
        }
        if (lane == 0) {
            // softmax denominator cancels: w1 = 1/(1+e^{l2-l1}), w2 = e^{l2-l1}*w1
            float p2  = expf(m2 - m1);
            float inv = 1.f / (1.f + p2);
            float w1  = inv       * escale[i1];
            float w2  = p2 * inv  * escale[i2];
            int p;
            p = atomicAdd(&g_cnt[i1], 1);
            g_tok[i1][p] = tok; g_wt[i1][p] = w1; g_kis[i1][p] = 0;
            p = atomicAdd(&g_cnt[i2], 1);
            g_tok[i2][p] = tok; g_wt[i2][p] = w2; g_kis[i2][p] = 1;
        }
    }
}

// ---------------- K2a: gate GEMM + GeGLU ----------------
// grid = EE(e) x 8(hc: 64 h-pairs each) x 16(token tiles of 32)
// thread micro-tile: 4 tokens x 2 h-pairs x 2 branches = 16 accumulators
__global__ __launch_bounds__(TPB) void k2a_gate(
    const float* __restrict__ x, const float* __restrict__ Gate)
{
    const int b    = blockIdx.x;
    const int tile = b & 15;
    const int hc   = (b >> 4) & 7;
    const int e    = b >> 7;

    const int n  = g_cnt[e];
    const int t0 = tile * 32;
    if (t0 >= n) return;
    const int nt = min(32, n - t0);

    __shared__ __align__(16) float sX[32][68];    // stride 68 ≡ 0 mod 4: float4-safe
    __shared__ __align__(16) float sG[128][68];
    __shared__ int   stok[32];
    __shared__ float swgt[32];

    const int tid = threadIdx.x;
    if (tid < 32) {
        const bool v = (tid < nt);
        stok[tid] = v ? g_tok[e][t0 + tid] : -1;
        swgt[tid] = v ? g_wt[e][t0 + tid]  : 0.f;
    }
    __syncthreads();

    const int tt = tid & 7;    // token group: tokens tt*4..tt*4+3
    const int hh = tid >> 3;   // pair group:  pairs hh*2, hh*2+1

    float acc[4][2][2];
    #pragma unroll
    for (int i = 0; i < 4; i++)
        #pragma unroll
        for (int j = 0; j < 2; j++) { acc[i][j][0] = 0.f; acc[i][j][1] = 0.f; }

    const float* Gexp = Gate + (size_t)e * GROWS * DD;
    const int h0 = hc * 64;

    for (int c = 0; c < 8; c++) {        // d-chunks of 64
        // stage X chunk: 32 tok x 64 d (512 float4, 2 per thread)
        #pragma unroll
        for (int r = 0; r < 2; r++) {
            int f    = tid + r * 256;
            int row  = f >> 4;
            int col4 = f & 15;
            int tk   = stok[row];
            float4 v = make_float4(0.f, 0.f, 0.f, 0.f);
            if (tk >= 0)
                v = ((const float4*)(x + (size_t)tk * DD + c * 64))[col4];
            *(float4*)&sX[row][col4 * 4] = v;
        }
        // stage G chunk: rows 0..63 = branch0 h0..h0+63, rows 64..127 = branch1
        #pragma unroll
        for (int r = 0; r < 8; r++) {
            int f    = tid + r * 256;       // 0..2047
            int row  = f >> 4;              // 0..127
            int col4 = f & 15;
            int grow = (row < 64) ? (h0 + row) : (HH + h0 + row - 64);
            float4 v = ((const float4*)(Gexp + (size_t)grow * DD + c * 64))[col4];
            *(float4*)&sG[row][col4 * 4] = v;
        }
        __syncthreads();

        #pragma unroll
        for (int dv = 0; dv < 16; dv++) {
            float4 xv[4], gv[2][2];
            #pragma unroll
            for (int i = 0; i < 4; i++) xv[i] = *(const float4*)&sX[tt * 4 + i][dv * 4];
            #pragma unroll
            for (int j = 0; j < 2; j++) {
                gv[j][0] = *(const float4*)&sG[hh * 2 + j][dv * 4];
                gv[j][1] = *(const float4*)&sG[64 + hh * 2 + j][dv * 4];
            }
            #pragma unroll
            for (int i = 0; i < 4; i++)
                #pragma unroll
                for (int j = 0; j < 2; j++)
                    #pragma unroll
                    for (int g = 0; g < 2; g++) {
                        acc[i][j][g] = fmaf(xv[i].x, gv[j][g].x, acc[i][j][g]);
                        acc[i][j][g] = fmaf(xv[i].y, gv[j][g].y, acc[i][j][g]);
                        acc[i][j][g] = fmaf(xv[i].z, gv[j][g].z, acc[i][j][g]);
                        acc[i][j][g] = fmaf(xv[i].w, gv[j][g].w, acc[i][j][g]);
                    }
        }
        __syncthreads();
    }

    #pragma unroll
    for (int i = 0; i < 4; i++) {
        const int li = tt * 4 + i;
        if (li < nt) {
            const float w  = swgt[li];
            const int   sl = t0 + li;
            #pragma unroll
            for (int j = 0; j < 2; j++) {
                const int h = h0 + hh * 2 + j;
                g_act[e][sl][h] = gelu_tanh(acc[i][j][0]) * acc[i][j][1] * w;
            }
        }
    }
}

// ---------------- K2b: down-projection GEMM ----------------
// grid = EE(e) x 4(dc: 128 d each) x 16(token tiles of 32)
// thread micro-tile: 4 tokens x 4 d
__global__ __launch_bounds__(TPB) void k2b_down(
    const float* __restrict__ Lin)
{
    const int b    = blockIdx.x;
    const int tile = b & 15;
    const int dc   = (b >> 4) & 3;
    const int e    = b >> 6;

    const int n  = g_cnt[e];
    const int t0 = tile * 32;
    if (t0 >= n) return;
    const int nt = min(32, n - t0);

    // sA stride 65: scalar staging (no float4 writes — 65 % 4 != 0),
    // and 65 % 32 == 1 makes the FMA-loop row reads conflict-free.
    __shared__ float sA[32][65];
    __shared__ __align__(16) float sL[64][132];
    __shared__ int   stok[32];
    __shared__ unsigned char skis[32];

    const int tid = threadIdx.x;
    if (tid < 32) {
        const bool v = (tid < nt);
        stok[tid] = v ? g_tok[e][t0 + tid] : -1;
        skis[tid] = v ? g_kis[e][t0 + tid] : 0;
    }
    __syncthreads();

    const int tt = tid & 7;    // tokens tt*4..+3
    const int dd = tid >> 3;   // d = dc*128 + dd*4 .. +3

    float acc[4][4];
    #pragma unroll
    for (int i = 0; i < 4; i++)
        #pragma unroll
        for (int j = 0; j < 4; j++) acc[i][j] = 0.f;

    const float* Lexp = Lin + (size_t)e * HH * DD;

    for (int c = 0; c < 8; c++) {        // h-chunks of 64
        // stage A: 32 tok x 64 h, SCALAR (2048 floats, 8 per thread, coalesced)
        #pragma unroll
        for (int r = 0; r < 8; r++) {
            int f   = tid + r * 256;       // 0..2047
            int row = f >> 6;              // 0..31
            int col = f & 63;
            sA[row][col] = (row < nt) ? g_act[e][t0 + row][c * 64 + col] : 0.f;
        }
        // stage Lin: 64 h x 128 d (2048 float4, 8 per thread)
        #pragma unroll
        for (int r = 0; r < 8; r++) {
            int f    = tid + r * 256;
            int row  = f >> 5;              // 0..63   (128 cols = 32 f4)
            int col4 = f & 31;
            float4 v = ((const float4*)(Lexp + (size_t)(c * 64 + row) * DD + dc * 128))[col4];
            *(float4*)&sL[row][col4 * 4] = v;
        }
        __syncthreads();

        #pragma unroll
        for (int k = 0; k < 64; k++) {
            float4 lv = *(const float4*)&sL[k][dd * 4];
            float  a0 = sA[tt * 4 + 0][k];
            float  a1 = sA[tt * 4 + 1][k];
            float  a2 = sA[tt * 4 + 2][k];
            float  a3 = sA[tt * 4 + 3][k];
            acc[0][0] = fmaf(a0, lv.x, acc[0][0]); acc[0][1] = fmaf(a0, lv.y, acc[0][1]);
            acc[0][2] = fmaf(a0, lv.z, acc[0][2]); acc[0][3] = fmaf(a0, lv.w, acc[0][3]);
            acc[1][0] = fmaf(a1, lv.x, acc[1][0]); acc[1][1] = fmaf(a1, lv.y, acc[1][1]);
            acc[1][2] = fmaf(a1, lv.z, acc[1][2]); acc[1][3] = fmaf(a1, lv.w, acc[1][3]);
            acc[2][0] = fmaf(a2, lv.x, acc[2][0]); acc[2][1] = fmaf(a2, lv.y, acc[2][1]);
            acc[2][2] = fmaf(a2, lv.z, acc[2][2]); acc[2][3] = fmaf(a2, lv.w, acc[2][3]);
            acc[3][0] = fmaf(a3, lv.x, acc[3][0]); acc[3][1] = fmaf(a3, lv.y, acc[3][1]);
            acc[3][2] = fmaf(a3, lv.z, acc[3][2]); acc[3][3] = fmaf(a3, lv.w, acc[3][3]);
        }
        __syncthreads();
    }

    #pragma unroll
    for (int i = 0; i < 4; i++) {
        const int li = tt * 4 + i;
        if (li < nt) {
            const int tok = stok[li];
            const int ki  = skis[li];
            float4 v = make_float4(acc[i][0], acc[i][1], acc[i][2], acc[i][3]);
            *(float4*)(&g_buf[ki][(size_t)tok * DD + dc * 128 + dd * 4]) = v;
        }
    }
}

// ---------------- K3: combine ki=0 and ki=1 contributions ----------------
__global__ void k3_sum(float* __restrict__ out) {
    const int i = blockIdx.x * blockDim.x + threadIdx.x;   // float4 index
    float4 a = ((const float4*)g_buf[0])[i];
    float4 b = ((const float4*)g_buf[1])[i];
    float4 r = make_float4(a.x + b.x, a.y + b.y, a.z + b.z, a.w + b.w);
    ((float4*)out)[i] = r;
}

// ---------------- dispatch ----------------
extern "C" void kernel_launch(void* const* d_in, const int* in_sizes, int n_in,
                              void* d_out, int out_size) {
    // Rank-based binding (sizes strictly distinct, ranking invariant to units):
    //   escale(32) < router_scale(512) < Wr(16384) < x(262144) < Lin(8388608) < Gate(16777216)
    const float *x, *rscale, *Wr, *Gate, *Lin, *escale;
    if (n_in == 6) {
        int ord[6] = {0, 1, 2, 3, 4, 5};
        for (int i = 1; i < 6; i++) {
            int v = ord[i], j = i - 1;
            while (j >= 0 && in_sizes[ord[j]] > in_sizes[v]) { ord[j + 1] = ord[j]; j--; }
            ord[j + 1] = v;
        }
        escale = (const float*)d_in[ord[0]];
        rscale = (const float*)d_in[ord[1]];
        Wr     = (const float*)d_in[ord[2]];
        x      = (const float*)d_in[ord[3]];
        Lin    = (const float*)d_in[ord[4]];
        Gate   = (const float*)d_in[ord[5]];
    } else {
        x      = (const float*)d_in[0];
        rscale = (const float*)d_in[1];
        Wr     = (const float*)d_in[2];
        Gate   = (const float*)d_in[3];
        Lin    = (const float*)d_in[4];
        escale = (const float*)d_in[5];
    }
    float* out = (float*)d_out;

    k0_zero<<<1, 32>>>();
    k1_router<<<LL, TPB>>>(x, rscale, Wr, escale);
    k2a_gate<<<EE * 8 * 16, TPB>>>(x, Gate);
    k2b_down<<<EE * 4 * 16, TPB>>>(Lin);
    k3_sum<<<(LL * DD / 4) / TPB, TPB>>>(out);
}

// round 15
// speedup vs baseline: 1.2247x; 1.2247x over previous
#include <cuda_runtime.h>
#include <cuda_bf16.h>

#define DD  512    // model dim
#define EE  32     // experts
#define HH  512    // hidden per gate branch
#define LL  512    // tokens
#define TPB 256

// ---------------- scratch (static device globals; no allocs) ----------------
__device__ int            g_cnt[EE];
__device__ int            g_tok[EE][LL];
__device__ float          g_wt [EE][LL];
__device__ unsigned char  g_kis[EE][LL];
__device__ __align__(16) float g_actT[EE][HH][LL];   // transposed: [expert][h][token-slot]
__device__ __align__(16) float g_buf[2][LL * DD];

// ---------------- helpers ----------------
__device__ __forceinline__ float warp_sum(float s) {
    #pragma unroll
    for (int o = 16; o; o >>= 1) s += __shfl_xor_sync(0xffffffffu, s, o);
    return s;
}
__device__ __forceinline__ float gelu_tanh(float g) {
    float inner = 0.7978845608028654f * (g + 0.044715f * g * g * g);
    return 0.5f * g * (1.f + tanhf(inner));
}
// acc (f4 over 4 tokens) += sum over 4 k of xv[k](tokens) * g.component(k)
__device__ __forceinline__ void fma_tok4_k4(float4& a, const float4* xv, float4 g) {
    a.x = fmaf(xv[0].x, g.x, a.x); a.x = fmaf(xv[1].x, g.y, a.x);
    a.x = fmaf(xv[2].x, g.z, a.x); a.x = fmaf(xv[3].x, g.w, a.x);
    a.y = fmaf(xv[0].y, g.x, a.y); a.y = fmaf(xv[1].y, g.y, a.y);
    a.y = fmaf(xv[2].y, g.z, a.y); a.y = fmaf(xv[3].y, g.w, a.y);
    a.z = fmaf(xv[0].z, g.x, a.z); a.z = fmaf(xv[1].z, g.y, a.z);
    a.z = fmaf(xv[2].z, g.z, a.z); a.z = fmaf(xv[3].z, g.w, a.z);
    a.w = fmaf(xv[0].w, g.x, a.w); a.w = fmaf(xv[1].w, g.y, a.w);
    a.w = fmaf(xv[2].w, g.z, a.w); a.w = fmaf(xv[3].w, g.w, a.w);
}
__device__ __forceinline__ void fma_tok4_s(float4& a, float4 xv, float s) {
    a.x = fmaf(xv.x, s, a.x); a.y = fmaf(xv.y, s, a.y);
    a.z = fmaf(xv.z, s, a.z); a.w = fmaf(xv.w, s, a.w);
}

// ---------------- K0: zero counters ----------------
__global__ void k0_zero() {
    if (threadIdx.x < EE) g_cnt[threadIdx.x] = 0;
}

// ---------------- K1: routing (one block per token) ----------------
__global__ __launch_bounds__(TPB) void k1_router(
    const float* __restrict__ x, const float* __restrict__ router_scale,
    const float* __restrict__ Wr, const float* __restrict__ escale)
{
    const int tok = blockIdx.x, t = threadIdx.x, lane = t & 31, wid = t >> 5;

    __shared__ float srin[DD];
    __shared__ float spart[8][EE];
    __shared__ float sred[8];

    const float* xrow = x + (size_t)tok * DD;
    float v0 = xrow[t], v1 = xrow[t + TPB];
    float ss = warp_sum(v0 * v0 + v1 * v1);
    if (lane == 0) sred[wid] = ss;
    __syncthreads();
    if (t == 0) {
        float tot = 0.f;
        #pragma unroll
        for (int i = 0; i < 8; i++) tot += sred[i];
        sred[0] = rsqrtf(tot / (float)DD + 1e-6f) * rsqrtf((float)DD);
    }
    __syncthreads();
    const float scl = sred[0];
    srin[t]       = v0 * scl * router_scale[t];
    srin[t + TPB] = v1 * scl * router_scale[t + TPB];
    __syncthreads();

    {
        float acc = 0.f;
        const int d0 = wid * 64;
        #pragma unroll 8
        for (int i = 0; i < 64; i++)
            acc = fmaf(srin[d0 + i], Wr[(d0 + i) * EE + lane], acc);
        spart[wid][lane] = acc;
    }
    __syncthreads();

    if (wid == 0) {
        float l = 0.f;
        #pragma unroll
        for (int i = 0; i < 8; i++) l += spart[i][lane];

        float m1 = l; int i1 = lane;
        #pragma unroll
        for (int o = 16; o; o >>= 1) {
            float om = __shfl_xor_sync(0xffffffffu, m1, o);
            int   oi = __shfl_xor_sync(0xffffffffu, i1, o);
            if (om > m1 || (om == m1 && oi < i1)) { m1 = om; i1 = oi; }
        }
        float l2 = (lane == i1) ? -3.4e38f : l;
        float m2 = l2; int i2 = lane;
        #pragma unroll
        for (int o = 16; o; o >>= 1) {
            float om = __shfl_xor_sync(0xffffffffu, m2, o);
            int   oi = __shfl_xor_sync(0xffffffffu, i2, o);
            if (om > m2 || (om == m2 && oi < i2)) { m2 = om; i2 = oi; }
        }
        if (lane == 0) {
            float p2  = expf(m2 - m1);
            float inv = 1.f / (1.f + p2);
            float w1  = inv      * escale[i1];
            float w2  = p2 * inv * escale[i2];
            int p;
            p = atomicAdd(&g_cnt[i1], 1);
            g_tok[i1][p] = tok; g_wt[i1][p] = w1; g_kis[i1][p] = 0;
            p = atomicAdd(&g_cnt[i2], 1);
            g_tok[i2][p] = tok; g_wt[i2][p] = w2; g_kis[i2][p] = 1;
        }
    }
}

// ---------------- K2a: gate GEMM + GeGLU ----------------
// grid = e(32) x hc(8) x tile(16); 128 threads
// thread: 4 tokens (f4 components) x 4 h x 2 branches; k-blocked by 4
__global__ __launch_bounds__(128) void k2a_gate(
    const float* __restrict__ x, const float* __restrict__ Gate)
{
    const int b    = blockIdx.x;
    const int tile = b & 15;
    const int hc   = (b >> 4) & 7;
    const int e    = b >> 7;

    const int n  = g_cnt[e];
    const int t0 = tile * 32;
    if (t0 >= n) return;
    const int nt = min(32, n - t0);

    __shared__ __align__(16) float sXT[64][36];   // [k][token]  (transposed)
    __shared__ __align__(16) float sG[128][68];   // [grow][k]   (row-major)
    __shared__ int   stok[32];
    __shared__ float swgt[32];

    const int tid = threadIdx.x;
    if (tid < 32) {
        const bool v = (tid < nt);
        stok[tid] = v ? g_tok[e][t0 + tid] : -1;
        swgt[tid] = v ? g_wt[e][t0 + tid]  : 0.f;
    }
    __syncthreads();

    const int tt = tid & 7;     // token group: tokens tt*4 .. tt*4+3 (f4 comps)
    const int rr = tid >> 3;    // h group: h_local rr*4 .. rr*4+3
    const int h0 = hc * 64;
    const float* Gexp = Gate + (size_t)e * 2 * HH * DD;

    float4 acc0[4], acc1[4];
    #pragma unroll
    for (int j = 0; j < 4; j++) {
        acc0[j] = make_float4(0.f, 0.f, 0.f, 0.f);
        acc1[j] = make_float4(0.f, 0.f, 0.f, 0.f);
    }

    for (int c = 0; c < 8; c++) {          // k-chunks of 64
        // stage X transposed: 32 tok x 64 k -> sXT[k][tok]
        #pragma unroll
        for (int r = 0; r < 4; r++) {
            int f = tid + r * 128, row = f >> 4, col4 = f & 15;
            int tk = stok[row];
            float4 v = make_float4(0.f, 0.f, 0.f, 0.f);
            if (tk >= 0)
                v = *(const float4*)(x + (size_t)tk * DD + c * 64 + col4 * 4);
            sXT[col4 * 4 + 0][row] = v.x;
            sXT[col4 * 4 + 1][row] = v.y;
            sXT[col4 * 4 + 2][row] = v.z;
            sXT[col4 * 4 + 3][row] = v.w;
        }
        // stage G row-major: rows 0..63 = branch0 h0.., 64..127 = branch1
        #pragma unroll
        for (int r = 0; r < 16; r++) {
            int f = tid + r * 128, row = f >> 4, col4 = f & 15;
            int grow = (row < 64) ? (h0 + row) : (HH + h0 + row - 64);
            *(float4*)&sG[row][col4 * 4] =
                *(const float4*)(Gexp + (size_t)grow * DD + c * 64 + col4 * 4);
        }
        __syncthreads();

        #pragma unroll 2
        for (int kb = 0; kb < 16; kb++) {   // 4 k per iteration
            float4 xv[4];
            #pragma unroll
            for (int u = 0; u < 4; u++)
                xv[u] = *(const float4*)&sXT[kb * 4 + u][tt * 4];
            float4 g0[4], g1[4];
            #pragma unroll
            for (int j = 0; j < 4; j++) {
                g0[j] = *(const float4*)&sG[rr * 4 + j][kb * 4];
                g1[j] = *(const float4*)&sG[64 + rr * 4 + j][kb * 4];
            }
            #pragma unroll
            for (int j = 0; j < 4; j++) {
                fma_tok4_k4(acc0[j], xv, g0[j]);
                fma_tok4_k4(acc1[j], xv, g1[j]);
            }
        }
        __syncthreads();
    }

    // epilogue: GeGLU * weight, store token-contiguous f4 (padding slots get 0)
    #pragma unroll
    for (int j = 0; j < 4; j++) {
        const int h = h0 + rr * 4 + j;
        float4 a0 = acc0[j], a1 = acc1[j], o;
        o.x = gelu_tanh(a0.x) * a1.x * swgt[tt * 4 + 0];
        o.y = gelu_tanh(a0.y) * a1.y * swgt[tt * 4 + 1];
        o.z = gelu_tanh(a0.z) * a1.z * swgt[tt * 4 + 2];
        o.w = gelu_tanh(a0.w) * a1.w * swgt[tt * 4 + 3];
        *(float4*)&g_actT[e][h][t0 + tt * 4] = o;
    }
}

// ---------------- K2b: down-projection GEMM ----------------
// grid = e(32) x dc(4) x tile(16); 128 threads
// thread: 4 tokens (f4 comps) x 8 d; h-blocked by 4
__global__ __launch_bounds__(128) void k2b_down(
    const float* __restrict__ Lin)
{
    const int b    = blockIdx.x;
    const int tile = b & 15;
    const int dc   = (b >> 4) & 3;
    const int e    = b >> 6;

    const int n  = g_cnt[e];
    const int t0 = tile * 32;
    if (t0 >= n) return;
    const int nt = min(32, n - t0);

    __shared__ __align__(16) float sA[64][36];    // [h][token]  (already transposed)
    __shared__ __align__(16) float sL[64][132];   // [h][d]
    __shared__ int   stok[32];
    __shared__ unsigned char skis[32];

    const int tid = threadIdx.x;
    if (tid < 32) {
        const bool v = (tid < nt);
        stok[tid] = v ? g_tok[e][t0 + tid] : -1;
        skis[tid] = v ? g_kis[e][t0 + tid] : 0;
    }
    __syncthreads();

    const int tt = tid & 7;     // token group
    const int dd = tid >> 3;    // d group: d = dc*128 + dd*8 .. +7
    const float* Lexp = Lin + (size_t)e * HH * DD;

    float4 accA[4], accB[4];
    #pragma unroll
    for (int j = 0; j < 4; j++) {
        accA[j] = make_float4(0.f, 0.f, 0.f, 0.f);
        accB[j] = make_float4(0.f, 0.f, 0.f, 0.f);
    }

    for (int c = 0; c < 8; c++) {          // h-chunks of 64
        // stage A from g_actT (token-contiguous rows): 64h x 32tok
        #pragma unroll
        for (int r = 0; r < 4; r++) {
            int f = tid + r * 128, row = f >> 3, col4 = f & 7;
            *(float4*)&sA[row][col4 * 4] =
                *(const float4*)&g_actT[e][c * 64 + row][t0 + col4 * 4];
        }
        // stage Lin: 64h x 128d
        #pragma unroll
        for (int r = 0; r < 16; r++) {
            int f = tid + r * 128, row = f >> 5, col4 = f & 31;
            *(float4*)&sL[row][col4 * 4] =
                *(const float4*)(Lexp + (size_t)(c * 64 + row) * DD + dc * 128 + col4 * 4);
        }
        __syncthreads();

        #pragma unroll 2
        for (int hb = 0; hb < 16; hb++) {   // 4 h per iteration
            float4 xv[4], la[4], lb[4];
            #pragma unroll
            for (int u = 0; u < 4; u++) {
                xv[u] = *(const float4*)&sA[hb * 4 + u][tt * 4];
                la[u] = *(const float4*)&sL[hb * 4 + u][dd * 8];
                lb[u] = *(const float4*)&sL[hb * 4 + u][dd * 8 + 4];
            }
            #pragma unroll
            for (int u = 0; u < 4; u++) {
                fma_tok4_s(accA[0], xv[u], la[u].x);
                fma_tok4_s(accA[1], xv[u], la[u].y);
                fma_tok4_s(accA[2], xv[u], la[u].z);
                fma_tok4_s(accA[3], xv[u], la[u].w);
                fma_tok4_s(accB[0], xv[u], lb[u].x);
                fma_tok4_s(accB[1], xv[u], lb[u].y);
                fma_tok4_s(accB[2], xv[u], lb[u].z);
                fma_tok4_s(accB[3], xv[u], lb[u].w);
            }
        }
        __syncthreads();
    }

    // epilogue: transpose acc -> per-token f4 pairs, store to g_buf[ki]
    const int d0 = dc * 128 + dd * 8;
    #pragma unroll
    for (int cc = 0; cc < 4; cc++) {
        const int li = tt * 4 + cc;
        if (li < nt) {
            const int tok = stok[li];
            const int ki  = skis[li];
            const float* a = (const float*)accA;
            const float* bq = (const float*)accB;
            float4 w0 = make_float4(a[0 * 4 + cc],  a[1 * 4 + cc],  a[2 * 4 + cc],  a[3 * 4 + cc]);
            float4 w1 = make_float4(bq[0 * 4 + cc], bq[1 * 4 + cc], bq[2 * 4 + cc], bq[3 * 4 + cc]);
            *(float4*)&g_buf[ki][(size_t)tok * DD + d0]     = w0;
            *(float4*)&g_buf[ki][(size_t)tok * DD + d0 + 4] = w1;
        }
    }
}

// ---------------- K3: combine ----------------
__global__ void k3_sum(float* __restrict__ out) {
    const int i = blockIdx.x * blockDim.x + threadIdx.x;
    float4 a = ((const float4*)g_buf[0])[i];
    float4 b = ((const float4*)g_buf[1])[i];
    ((float4*)out)[i] = make_float4(a.x + b.x, a.y + b.y, a.z + b.z, a.w + b.w);
}

// ---------------- dispatch ----------------
extern "C" void kernel_launch(void* const* d_in, const int* in_sizes, int n_in,
                              void* d_out, int out_size) {
    const float *x, *rscale, *Wr, *Gate, *Lin, *escale;
    if (n_in == 6) {
        int ord[6] = {0, 1, 2, 3, 4, 5};
        for (int i = 1; i < 6; i++) {
            int v = ord[i], j = i - 1;
            while (j >= 0 && in_sizes[ord[j]] > in_sizes[v]) { ord[j + 1] = ord[j]; j--; }
            ord[j + 1] = v;
        }
        escale = (const float*)d_in[ord[0]];
        rscale = (const float*)d_in[ord[1]];
        Wr     = (const float*)d_in[ord[2]];
        x      = (const float*)d_in[ord[3]];
        Lin    = (const float*)d_in[ord[4]];
        Gate   = (const float*)d_in[ord[5]];
    } else {
        x      = (const float*)d_in[0];
        rscale = (const float*)d_in[1];
        Wr     = (const float*)d_in[2];
        Gate   = (const float*)d_in[3];
        Lin    = (const float*)d_in[4];
        escale = (const float*)d_in[5];
    }
    float* out = (float*)d_out;

    k0_zero<<<1, 32>>>();
    k1_router<<<LL, TPB>>>(x, rscale, Wr, escale);
    k2a_gate<<<EE * 8 * 16, 128>>>(x, Gate);
    k2b_down<<<EE * 4 * 16, 128>>>(Lin);
    k3_sum<<<(LL * DD / 4) / TPB, TPB>>>(out);
}